// round 13
// baseline (speedup 1.0000x reference)
#include <cuda_runtime.h>

#define Bv 4
#define Sv 512
#define Hv 768
#define Dv 24
#define Mv 96
#define OHv 768
#define Rv (Bv*Sv)        /* 2048 */
#define K3H (3*Hv)        /* 2304 */

// ---------------- scratch (device globals; no runtime allocation) ----------------
__device__ float g_Zj[Rv*Dv];
__device__ float g_Zi[Rv*Dv];
__device__ float g_P[(long)Bv*Sv*Sv];  // logits -> probs (4 MB)
__device__ float g_ctx[(long)Rv*Hv];
__device__ float g_msgin[(long)Rv*K3H];
__device__ float g_hid1[(long)Rv*OHv];
__device__ __align__(16) unsigned g_Wf[12*12*32*2];  // permuted tf32 weights, fragment layout
__device__ float2 g_pw[Mv];                           // (w2[m], b1[m])

// ---------------- tf32 helpers ----------------
__device__ __forceinline__ unsigned f2tf(float x) {
    unsigned r;
    asm("cvt.rna.tf32.f32 %0, %1;" : "=r"(r) : "f"(x));
    return r;
}
__device__ __forceinline__ void mma_tf32(float& c0, float& c1, float& c2, float& c3,
                                         unsigned a0, unsigned a1, unsigned a2, unsigned a3,
                                         unsigned b0, unsigned b1) {
    asm volatile("mma.sync.aligned.m16n8k8.row.col.f32.tf32.tf32.f32 "
                 "{%0,%1,%2,%3},{%4,%5,%6,%7},{%8,%9},{%0,%1,%2,%3};"
                 : "+f"(c0), "+f"(c1), "+f"(c2), "+f"(c3)
                 : "r"(a0), "r"(a1), "r"(a2), "r"(a3), "r"(b0), "r"(b1));
}

// ---------------- K0: one-time weight prep (permute + tf32 + fragment layout) ----------------
__global__ __launch_bounds__(256) void k_prep(const float* __restrict__ sw1,
                                              const float* __restrict__ sw2,
                                              const float* __restrict__ sb1)
{
    int idx = blockIdx.x * 256 + threadIdx.x;
    if (idx < Mv * 96) {
        int m = idx / 96, k = idx - m * 96;
        int src;
        if (k < 24)      src = 48 + k;
        else if (k < 48) src = 72 + (k - 24);
        else if (k < 72) src = k - 48;
        else             src = 24 + (k - 72);
        int kt = k >> 3, kr = k & 7, c = kr & 3, reg = kr >> 2;
        int nt = m >> 3, g = m & 7;
        g_Wf[((kt*12 + nt)*32 + g*4 + c)*2 + reg] = f2tf(sw1[m * 96 + src]);
    }
    if (blockIdx.x == 0 && threadIdx.x < Mv)
        g_pw[threadIdx.x] = make_float2(sw2[threadIdx.x], sb1[threadIdx.x]);
}

// ---------------- K1: projections Zj/Zi (4 rows per block for weight L1 reuse) ----------------
__global__ __launch_bounds__(256) void k_proj(const float* __restrict__ Hj,
                                              const float* __restrict__ Hi,
                                              const float* __restrict__ pj,
                                              const float* __restrict__ pi)
{
    int row0  = blockIdx.x * 4;   // 4 consecutive rows
    int which = blockIdx.y;
    const float* Hm = which ? Hi : Hj;
    const float* Pw = which ? pi : pj;
    float* Zo = which ? g_Zi : g_Zj;
    __shared__ float sh[4][Hv];
    int tid = threadIdx.x;
    for (int i = tid; i < 4 * Hv; i += 256)
        sh[i / Hv][i % Hv] = Hm[(long)row0 * Hv + i];
    __syncthreads();
    int warp = tid >> 5, lane = tid & 31;
    // 96 tasks = 24 d x 4 rows, d-major so same-d tasks reuse the L1-resident weight row
    for (int task = warp; task < 96; task += 8) {
        int d = task >> 2, r = task & 3;
        const float* pr = Pw + d * Hv;
        const float* hr = sh[r];
        float acc = 0.f;
        for (int i = lane; i < Hv; i += 32) acc += hr[i] * pr[i];
        #pragma unroll
        for (int o = 16; o; o >>= 1) acc += __shfl_down_sync(0xFFFFFFFFu, acc, o);
        if (lane == 0) Zo[(row0 + r) * Dv + d] = acc;
    }
}

// ---------------- K2: pairwise MLP -> logits via tf32 MMA (proven R9 version) ----------------
#define ST 8
#define TT 32
__global__ __launch_bounds__(256) void k_logits3(const float* __restrict__ sb2)
{
    __shared__ __align__(16) unsigned Ws[12*12*32*2];   // 36 KB fragment-layout weights
    __shared__ float2 pw[Mv];
    __shared__ float Zjs[ST][25];
    __shared__ float Zis[TT][25];
    int b  = blockIdx.z;
    int s0 = blockIdx.y * ST;
    int t0 = blockIdx.x * TT;
    int tid = threadIdx.x;

    {   // stage weights: 9216 u32 = 2304 uint4, 9 per thread
        const uint4* src = (const uint4*)g_Wf;
        uint4* dst = (uint4*)Ws;
        #pragma unroll
        for (int i = 0; i < 9; i++) dst[tid + i * 256] = src[tid + i * 256];
    }
    if (tid < Mv) pw[tid] = g_pw[tid];
    for (int i = tid; i < ST * Dv; i += 256)
        Zjs[i / Dv][i % Dv] = g_Zj[(b * Sv + s0 + i / Dv) * Dv + (i % Dv)];
    for (int i = tid; i < TT * Dv; i += 256)
        Zis[i / Dv][i % Dv] = g_Zi[(b * Sv + t0 + i / Dv) * Dv + (i % Dv)];
    __syncthreads();

    int wid  = tid >> 5, lane = tid & 31;
    int g = lane >> 2, c = lane & 3;
    float b2 = sb2[0];

    #pragma unroll
    for (int tt = 0; tt < 2; tt++) {
        const int toff = tt * 16;
        float acc[12][4];
        #pragma unroll
        for (int nt = 0; nt < 12; nt++)
            #pragma unroll
            for (int q = 0; q < 4; q++) acc[nt][q] = 0.f;

        #pragma unroll
        for (int ks = 0; ks < 12; ks++) {
            const int k0 = ks * 8;
            const int op = k0 / 24;
            const int d0 = k0 % 24;
            int d  = d0 + c;
            int d4 = d0 + c + 4;
            unsigned a0, a1, a2, a3;
            if (op == 0) {               // Zj * Zi
                float zj = Zjs[wid][d], zj4 = Zjs[wid][d4];
                a0 = f2tf(zj  * Zis[toff + g][d]);   a1 = f2tf(zj  * Zis[toff + g + 8][d]);
                a2 = f2tf(zj4 * Zis[toff + g][d4]);  a3 = f2tf(zj4 * Zis[toff + g + 8][d4]);
            } else if (op == 1) {        // |Zj - Zi|
                float zj = Zjs[wid][d], zj4 = Zjs[wid][d4];
                a0 = f2tf(fabsf(zj  - Zis[toff + g][d]));   a1 = f2tf(fabsf(zj  - Zis[toff + g + 8][d]));
                a2 = f2tf(fabsf(zj4 - Zis[toff + g][d4]));  a3 = f2tf(fabsf(zj4 - Zis[toff + g + 8][d4]));
            } else if (op == 2) {        // Zj (t-invariant)
                unsigned u = f2tf(Zjs[wid][d]), u4 = f2tf(Zjs[wid][d4]);
                a0 = u; a1 = u; a2 = u4; a3 = u4;
            } else {                     // Zi
                a0 = f2tf(Zis[toff + g][d]);   a1 = f2tf(Zis[toff + g + 8][d]);
                a2 = f2tf(Zis[toff + g][d4]);  a3 = f2tf(Zis[toff + g + 8][d4]);
            }
            #pragma unroll
            for (int nt = 0; nt < 12; nt++) {
                uint2 bv = *(const uint2*)&Ws[((ks*12 + nt)*32 + lane)*2];
                mma_tf32(acc[nt][0], acc[nt][1], acc[nt][2], acc[nt][3],
                         a0, a1, a2, a3, bv.x, bv.y);
            }
        }

        float r0 = 0.f, r1 = 0.f;
        #pragma unroll
        for (int nt = 0; nt < 12; nt++) {
            int m = nt * 8 + c * 2;
            float2 p0 = pw[m], p1 = pw[m + 1];
            r0 += fmaxf(acc[nt][0] + p0.y, 0.f) * p0.x + fmaxf(acc[nt][1] + p1.y, 0.f) * p1.x;
            r1 += fmaxf(acc[nt][2] + p0.y, 0.f) * p0.x + fmaxf(acc[nt][3] + p1.y, 0.f) * p1.x;
        }
        r0 += __shfl_xor_sync(0xFFFFFFFFu, r0, 1);
        r0 += __shfl_xor_sync(0xFFFFFFFFu, r0, 2);
        r1 += __shfl_xor_sync(0xFFFFFFFFu, r1, 1);
        r1 += __shfl_xor_sync(0xFFFFFFFFu, r1, 2);
        if (c == 0) {
            long base = ((long)(b * Sv + s0 + wid)) * Sv + t0 + toff;
            g_P[base + g]     = r0 + b2;
            g_P[base + g + 8] = r1 + b2;
        }
    }
}

// ---------------- K3: masked softmax over t ----------------
__global__ __launch_bounds__(256) void k_softmax(const float* __restrict__ mask)
{
    int row = blockIdx.x;
    int b = row >> 9;
    float* p = g_P + (long)row * Sv;
    int tid = threadIdx.x;
    __shared__ float red[256];
    const float NEG = -3.402823466e38f;
    float x0 = p[tid]       + (1.f - mask[b*Sv + tid])       * NEG;
    float x1 = p[tid + 256] + (1.f - mask[b*Sv + tid + 256]) * NEG;
    float mx = fmaxf(x0, x1);
    red[tid] = mx; __syncthreads();
    for (int o = 128; o; o >>= 1) { if (tid < o) red[tid] = fmaxf(red[tid], red[tid+o]); __syncthreads(); }
    mx = red[0];
    __syncthreads();
    float e0 = __expf(x0 - mx), e1 = __expf(x1 - mx);
    red[tid] = e0 + e1; __syncthreads();
    for (int o = 128; o; o >>= 1) { if (tid < o) red[tid] += red[tid+o]; __syncthreads(); }
    float inv = 1.f / red[0];
    p[tid]       = e0 * inv;
    p[tid + 256] = e1 * inv;
}

// ---------------- generic tf32 MMA GEMM v4: 32x64 tiles, 128 threads ----------------
// A row-major [M][lda]; B element [k][n] at Bp[k*sbk + n*sbn]
// (sbn==1: row-major KxN; sbk==1: NxK weights -> A@W.T)
// 4 warps (2 M x 2 N), warp = 16x32. Double-buffered. M%32==0, N%64==0, K%16==0.
// Smaller tile -> 2x block count -> ~21 warps/SM for our grids (latency hiding).
__global__ __launch_bounds__(128) void k_gemm_mma(
    const float* __restrict__ A, long sAb, int lda,
    const float* __restrict__ Bp, long sBb, int sbk, int sbn,
    float* __restrict__ C, long sCb, int ldc, int K,
    const float* __restrict__ bias, int dorelu,
    const float* __restrict__ alphap)
{
    __shared__ unsigned As[2][16][36];   // [k][m], tf32 bits (32 + 4 pad)
    __shared__ unsigned Bs[2][16][72];   // [k][n], tf32 bits (64 + 8 pad)
    int bz = blockIdx.z;
    A  += sAb * bz;  Bp += sBb * bz;  C += sCb * bz;
    int m0 = blockIdx.y * 32, n0 = blockIdx.x * 64;
    int tid  = threadIdx.x;
    int lane = tid & 31, wid = tid >> 5;
    int g = lane >> 2, c = lane & 3;
    int wm = (wid >> 1) * 16, wn = (wid & 1) * 32;

    int am  = tid >> 2, ak  = (tid & 3) * 4;   // A: one float4 per thread (32x16)
    int bk  = tid >> 3, bn  = (tid & 7) * 8;   // B row-major: 2 float4 per thread
    int bn2 = tid >> 1, bk2 = (tid & 1) * 8;   // B weight (NxK): 2 float4 per thread
    bool brow = (sbn == 1);
    int ktiles = K >> 4;

    {   // stage 0
        float4 v = *(const float4*)&A[(long)(m0 + am) * lda + ak];
        As[0][ak+0][am] = f2tf(v.x); As[0][ak+1][am] = f2tf(v.y);
        As[0][ak+2][am] = f2tf(v.z); As[0][ak+3][am] = f2tf(v.w);
        if (brow) {
            float4 w0 = *(const float4*)&Bp[(long)bk * sbk + n0 + bn];
            float4 w1 = *(const float4*)&Bp[(long)bk * sbk + n0 + bn + 4];
            Bs[0][bk][bn+0] = f2tf(w0.x); Bs[0][bk][bn+1] = f2tf(w0.y);
            Bs[0][bk][bn+2] = f2tf(w0.z); Bs[0][bk][bn+3] = f2tf(w0.w);
            Bs[0][bk][bn+4] = f2tf(w1.x); Bs[0][bk][bn+5] = f2tf(w1.y);
            Bs[0][bk][bn+6] = f2tf(w1.z); Bs[0][bk][bn+7] = f2tf(w1.w);
        } else {
            float4 w0 = *(const float4*)&Bp[(long)(n0 + bn2) * sbn + bk2];
            float4 w1 = *(const float4*)&Bp[(long)(n0 + bn2) * sbn + bk2 + 4];
            Bs[0][bk2+0][bn2] = f2tf(w0.x); Bs[0][bk2+1][bn2] = f2tf(w0.y);
            Bs[0][bk2+2][bn2] = f2tf(w0.z); Bs[0][bk2+3][bn2] = f2tf(w0.w);
            Bs[0][bk2+4][bn2] = f2tf(w1.x); Bs[0][bk2+5][bn2] = f2tf(w1.y);
            Bs[0][bk2+6][bn2] = f2tf(w1.z); Bs[0][bk2+7][bn2] = f2tf(w1.w);
        }
    }
    __syncthreads();

    float acc[4][4];
    #pragma unroll
    for (int nt = 0; nt < 4; nt++)
        #pragma unroll
        for (int q = 0; q < 4; q++) acc[nt][q] = 0.f;

    int buf = 0;
    for (int t = 0; t < ktiles; t++) {
        float4 v, w0, w1;
        bool has = (t + 1 < ktiles);
        if (has) {
            int k0 = (t + 1) << 4;
            v = *(const float4*)&A[(long)(m0 + am) * lda + k0 + ak];
            if (brow) {
                w0 = *(const float4*)&Bp[(long)(k0 + bk) * sbk + n0 + bn];
                w1 = *(const float4*)&Bp[(long)(k0 + bk) * sbk + n0 + bn + 4];
            } else {
                w0 = *(const float4*)&Bp[(long)(n0 + bn2) * sbn + k0 + bk2];
                w1 = *(const float4*)&Bp[(long)(n0 + bn2) * sbn + k0 + bk2 + 4];
            }
        }
        #pragma unroll
        for (int kk = 0; kk < 16; kk += 8) {
            unsigned a0 = As[buf][kk + c    ][wm + g];
            unsigned a1 = As[buf][kk + c    ][wm + g + 8];
            unsigned a2 = As[buf][kk + c + 4][wm + g];
            unsigned a3 = As[buf][kk + c + 4][wm + g + 8];
            #pragma unroll
            for (int nt = 0; nt < 4; nt++) {
                unsigned b0 = Bs[buf][kk + c    ][wn + nt * 8 + g];
                unsigned b1 = Bs[buf][kk + c + 4][wn + nt * 8 + g];
                mma_tf32(acc[nt][0], acc[nt][1], acc[nt][2], acc[nt][3],
                         a0, a1, a2, a3, b0, b1);
            }
        }
        if (has) {
            int nb = buf ^ 1;
            As[nb][ak+0][am] = f2tf(v.x); As[nb][ak+1][am] = f2tf(v.y);
            As[nb][ak+2][am] = f2tf(v.z); As[nb][ak+3][am] = f2tf(v.w);
            if (brow) {
                Bs[nb][bk][bn+0] = f2tf(w0.x); Bs[nb][bk][bn+1] = f2tf(w0.y);
                Bs[nb][bk][bn+2] = f2tf(w0.z); Bs[nb][bk][bn+3] = f2tf(w0.w);
                Bs[nb][bk][bn+4] = f2tf(w1.x); Bs[nb][bk][bn+5] = f2tf(w1.y);
                Bs[nb][bk][bn+6] = f2tf(w1.z); Bs[nb][bk][bn+7] = f2tf(w1.w);
            } else {
                Bs[nb][bk2+0][bn2] = f2tf(w0.x); Bs[nb][bk2+1][bn2] = f2tf(w0.y);
                Bs[nb][bk2+2][bn2] = f2tf(w0.z); Bs[nb][bk2+3][bn2] = f2tf(w0.w);
                Bs[nb][bk2+4][bn2] = f2tf(w1.x); Bs[nb][bk2+5][bn2] = f2tf(w1.y);
                Bs[nb][bk2+6][bn2] = f2tf(w1.z); Bs[nb][bk2+7][bn2] = f2tf(w1.w);
            }
            __syncthreads();
            buf = nb;
        }
    }

    float al = alphap ? *alphap : 1.f;
    #pragma unroll
    for (int i = 0; i < 2; i++) {
        int r = m0 + wm + g + i * 8;
        #pragma unroll
        for (int nt = 0; nt < 4; nt++) {
            int col = n0 + wn + nt * 8 + c * 2;
            float x0 = acc[nt][i*2 + 0], x1 = acc[nt][i*2 + 1];
            if (bias) { x0 += bias[col]; x1 += bias[col + 1]; }
            if (dorelu) { x0 = fmaxf(x0, 0.f); x1 = fmaxf(x1, 0.f); }
            *(float2*)&C[(long)r * ldc + col] = make_float2(x0 * al, x1 * al);
        }
    }
}

// ---------------- msg_in = [ctx, H_j, ctx*H_j] ----------------
__global__ __launch_bounds__(256) void k_msgin(const float* __restrict__ Hj)
{
    int i = blockIdx.x * 256 + threadIdx.x;
    if (i < Rv * Hv) {
        int r = i / Hv, h = i - r * Hv;
        float cx = g_ctx[i];
        float x = Hj[i];
        long base = (long)r * K3H + h;
        g_msgin[base]        = cx;
        g_msgin[base + Hv]   = x;
        g_msgin[base + 2*Hv] = cx * x;
    }
}

// ---------------- launch ----------------
extern "C" void kernel_launch(void* const* d_in, const int* in_sizes, int n_in,
                              void* d_out, int out_size)
{
    const float* Hj    = (const float*)d_in[0];
    const float* Hi    = (const float*)d_in[1];
    const float* mask  = (const float*)d_in[2];
    const float* pjw   = (const float*)d_in[3];
    const float* piw   = (const float*)d_in[4];
    const float* sw1   = (const float*)d_in[5];
    const float* sb1   = (const float*)d_in[6];
    const float* sw2   = (const float*)d_in[7];
    const float* sb2   = (const float*)d_in[8];
    const float* vw1   = (const float*)d_in[9];
    const float* vb1   = (const float*)d_in[10];
    const float* vw2   = (const float*)d_in[11];
    const float* vb2   = (const float*)d_in[12];
    const float* alpha = (const float*)d_in[13];
    float* out = (float*)d_out;
    (void)in_sizes; (void)n_in; (void)out_size;

    void *pP, *pCtx, *pMsg, *pH1;
    cudaGetSymbolAddress(&pP,   g_P);
    cudaGetSymbolAddress(&pCtx, g_ctx);
    cudaGetSymbolAddress(&pMsg, g_msgin);
    cudaGetSymbolAddress(&pH1,  g_hid1);

    // 0) weight prep (permute + tf32 + fragment layout)
    k_prep<<<36, 256>>>(sw1, sw2, sb1);
    // 1) projections (4 rows per block)
    k_proj<<<dim3(Rv/4, 2), 256>>>(Hj, Hi, pjw, piw);
    // 2) pairwise MLP logits
    k_logits3<<<dim3(Sv/TT, Sv/ST, Bv), 256>>>(sb2);
    // 3) masked softmax
    k_softmax<<<Rv, 256>>>(mask);
    // 4) ctx = probs @ H_i   (batched over b)
    k_gemm_mma<<<dim3(Hv/64, Sv/32, Bv), 128>>>(
        (const float*)pP, (long)Sv*Sv, Sv,
        Hi, (long)Sv*Hv, Hv, 1,
        (float*)pCtx, (long)Sv*Hv, Hv, Sv,
        nullptr, 0, nullptr);
    // 5) msg_in concat
    k_msgin<<<(Rv*Hv + 255)/256, 256>>>(Hj);
    // 6) hid1 = relu(msg_in @ v_w1.T + b1)
    k_gemm_mma<<<dim3(OHv/64, Rv/32, 1), 128>>>(
        (const float*)pMsg, 0L, K3H,
        vw1, 0L, 1, K3H,
        (float*)pH1, 0L, OHv, K3H,
        vb1, 1, nullptr);
    // 7) out = alpha * (hid1 @ v_w2.T + b2)
    k_gemm_mma<<<dim3(Hv/64, Rv/32, 1), 128>>>(
        (const float*)pH1, 0L, OHv,
        vw2, 0L, 1, OHv,
        out, 0L, Hv, OHv,
        vb2, 0, alpha);
}

// round 14
// speedup vs baseline: 1.2809x; 1.2809x over previous
#include <cuda_runtime.h>

#define Bv 4
#define Sv 512
#define Hv 768
#define Dv 24
#define Mv 96
#define OHv 768
#define Rv (Bv*Sv)        /* 2048 */
#define K3H (3*Hv)        /* 2304 */

// ---------------- scratch (device globals; no runtime allocation) ----------------
__device__ float g_Zj[Rv*Dv];
__device__ float g_Zi[Rv*Dv];
__device__ float g_P[(long)Bv*Sv*Sv];  // logits -> probs (4 MB)
__device__ float g_ctx[(long)Rv*Hv];
__device__ float g_hid1[(long)Rv*OHv];
__device__ __align__(16) unsigned g_Wf[12*12*32*2];  // permuted tf32 weights, fragment layout
__device__ float2 g_pw[Mv];                           // (w2[m], b1[m])

// ---------------- tf32 helpers ----------------
__device__ __forceinline__ unsigned f2tf(float x) {
    unsigned r;
    asm("cvt.rna.tf32.f32 %0, %1;" : "=r"(r) : "f"(x));
    return r;
}
__device__ __forceinline__ void mma_tf32(float& c0, float& c1, float& c2, float& c3,
                                         unsigned a0, unsigned a1, unsigned a2, unsigned a3,
                                         unsigned b0, unsigned b1) {
    asm volatile("mma.sync.aligned.m16n8k8.row.col.f32.tf32.tf32.f32 "
                 "{%0,%1,%2,%3},{%4,%5,%6,%7},{%8,%9},{%0,%1,%2,%3};"
                 : "+f"(c0), "+f"(c1), "+f"(c2), "+f"(c3)
                 : "r"(a0), "r"(a1), "r"(a2), "r"(a3), "r"(b0), "r"(b1));
}

// ---------------- K0: one-time weight prep (permute + tf32 + fragment layout) ----------------
__global__ __launch_bounds__(256) void k_prep(const float* __restrict__ sw1,
                                              const float* __restrict__ sw2,
                                              const float* __restrict__ sb1)
{
    int idx = blockIdx.x * 256 + threadIdx.x;
    if (idx < Mv * 96) {
        int m = idx / 96, k = idx - m * 96;
        int src;
        if (k < 24)      src = 48 + k;
        else if (k < 48) src = 72 + (k - 24);
        else if (k < 72) src = k - 48;
        else             src = 24 + (k - 72);
        int kt = k >> 3, kr = k & 7, c = kr & 3, reg = kr >> 2;
        int nt = m >> 3, g = m & 7;
        g_Wf[((kt*12 + nt)*32 + g*4 + c)*2 + reg] = f2tf(sw1[m * 96 + src]);
    }
    if (blockIdx.x == 0 && threadIdx.x < Mv)
        g_pw[threadIdx.x] = make_float2(sw2[threadIdx.x], sb1[threadIdx.x]);
}

// ---------------- K1: projections Zj/Zi (exact R9 version) ----------------
__global__ __launch_bounds__(256) void k_proj(const float* __restrict__ Hj,
                                              const float* __restrict__ Hi,
                                              const float* __restrict__ pj,
                                              const float* __restrict__ pi)
{
    int row   = blockIdx.x;
    int which = blockIdx.y;
    const float* Hm = which ? Hi : Hj;
    const float* Pw = which ? pi : pj;
    __shared__ float sh[Hv];
    int tid = threadIdx.x;
    const float* hrow = Hm + (long)row * Hv;
    for (int i = tid; i < Hv; i += 256) sh[i] = hrow[i];
    __syncthreads();
    int warp = tid >> 5, lane = tid & 31;
    for (int d = warp; d < Dv; d += 8) {
        const float* pr = Pw + d * Hv;
        float acc = 0.f;
        for (int i = lane; i < Hv; i += 32) acc += sh[i] * pr[i];
        #pragma unroll
        for (int o = 16; o; o >>= 1) acc += __shfl_down_sync(0xFFFFFFFFu, acc, o);
        if (lane == 0) (which ? g_Zi : g_Zj)[row * Dv + d] = acc;
    }
}

// ---------------- K2: pairwise MLP -> logits via tf32 MMA (R9 + TT=64) ----------------
// Block = 8 s x 64 t, FOUR sequential 8x16 subtiles reusing acc[12][4].
#define ST 8
#define TT 64
__global__ __launch_bounds__(256) void k_logits3(const float* __restrict__ sb2)
{
    __shared__ __align__(16) unsigned Ws[12*12*32*2];   // 36 KB fragment-layout weights
    __shared__ float2 pw[Mv];
    __shared__ float Zjs[ST][25];
    __shared__ float Zis[TT][25];
    int b  = blockIdx.z;
    int s0 = blockIdx.y * ST;
    int t0 = blockIdx.x * TT;
    int tid = threadIdx.x;

    {   // stage weights: 9216 u32 = 2304 uint4, 9 per thread
        const uint4* src = (const uint4*)g_Wf;
        uint4* dst = (uint4*)Ws;
        #pragma unroll
        for (int i = 0; i < 9; i++) dst[tid + i * 256] = src[tid + i * 256];
    }
    if (tid < Mv) pw[tid] = g_pw[tid];
    for (int i = tid; i < ST * Dv; i += 256)
        Zjs[i / Dv][i % Dv] = g_Zj[(b * Sv + s0 + i / Dv) * Dv + (i % Dv)];
    for (int i = tid; i < TT * Dv; i += 256)
        Zis[i / Dv][i % Dv] = g_Zi[(b * Sv + t0 + i / Dv) * Dv + (i % Dv)];
    __syncthreads();

    int wid  = tid >> 5, lane = tid & 31;
    int g = lane >> 2, c = lane & 3;
    float b2 = sb2[0];

    #pragma unroll
    for (int tt = 0; tt < TT/16; tt++) {
        const int toff = tt * 16;
        float acc[12][4];
        #pragma unroll
        for (int nt = 0; nt < 12; nt++)
            #pragma unroll
            for (int q = 0; q < 4; q++) acc[nt][q] = 0.f;

        #pragma unroll
        for (int ks = 0; ks < 12; ks++) {
            const int k0 = ks * 8;
            const int op = k0 / 24;
            const int d0 = k0 % 24;
            int d  = d0 + c;
            int d4 = d0 + c + 4;
            unsigned a0, a1, a2, a3;
            if (op == 0) {               // Zj * Zi
                float zj = Zjs[wid][d], zj4 = Zjs[wid][d4];
                a0 = f2tf(zj  * Zis[toff + g][d]);   a1 = f2tf(zj  * Zis[toff + g + 8][d]);
                a2 = f2tf(zj4 * Zis[toff + g][d4]);  a3 = f2tf(zj4 * Zis[toff + g + 8][d4]);
            } else if (op == 1) {        // |Zj - Zi|
                float zj = Zjs[wid][d], zj4 = Zjs[wid][d4];
                a0 = f2tf(fabsf(zj  - Zis[toff + g][d]));   a1 = f2tf(fabsf(zj  - Zis[toff + g + 8][d]));
                a2 = f2tf(fabsf(zj4 - Zis[toff + g][d4]));  a3 = f2tf(fabsf(zj4 - Zis[toff + g + 8][d4]));
            } else if (op == 2) {        // Zj (t-invariant)
                unsigned u = f2tf(Zjs[wid][d]), u4 = f2tf(Zjs[wid][d4]);
                a0 = u; a1 = u; a2 = u4; a3 = u4;
            } else {                     // Zi
                a0 = f2tf(Zis[toff + g][d]);   a1 = f2tf(Zis[toff + g + 8][d]);
                a2 = f2tf(Zis[toff + g][d4]);  a3 = f2tf(Zis[toff + g + 8][d4]);
            }
            #pragma unroll
            for (int nt = 0; nt < 12; nt++) {
                uint2 bv = *(const uint2*)&Ws[((ks*12 + nt)*32 + lane)*2];
                mma_tf32(acc[nt][0], acc[nt][1], acc[nt][2], acc[nt][3],
                         a0, a1, a2, a3, bv.x, bv.y);
            }
        }

        float r0 = 0.f, r1 = 0.f;
        #pragma unroll
        for (int nt = 0; nt < 12; nt++) {
            int m = nt * 8 + c * 2;
            float2 p0 = pw[m], p1 = pw[m + 1];
            r0 += fmaxf(acc[nt][0] + p0.y, 0.f) * p0.x + fmaxf(acc[nt][1] + p1.y, 0.f) * p1.x;
            r1 += fmaxf(acc[nt][2] + p0.y, 0.f) * p0.x + fmaxf(acc[nt][3] + p1.y, 0.f) * p1.x;
        }
        r0 += __shfl_xor_sync(0xFFFFFFFFu, r0, 1);
        r0 += __shfl_xor_sync(0xFFFFFFFFu, r0, 2);
        r1 += __shfl_xor_sync(0xFFFFFFFFu, r1, 1);
        r1 += __shfl_xor_sync(0xFFFFFFFFu, r1, 2);
        if (c == 0) {
            long base = ((long)(b * Sv + s0 + wid)) * Sv + t0 + toff;
            g_P[base + g]     = r0 + b2;
            g_P[base + g + 8] = r1 + b2;
        }
    }
}

// ---------------- K3: masked softmax over t ----------------
__global__ __launch_bounds__(256) void k_softmax(const float* __restrict__ mask)
{
    int row = blockIdx.x;
    int b = row >> 9;
    float* p = g_P + (long)row * Sv;
    int tid = threadIdx.x;
    __shared__ float red[256];
    const float NEG = -3.402823466e38f;
    float x0 = p[tid]       + (1.f - mask[b*Sv + tid])       * NEG;
    float x1 = p[tid + 256] + (1.f - mask[b*Sv + tid + 256]) * NEG;
    float mx = fmaxf(x0, x1);
    red[tid] = mx; __syncthreads();
    for (int o = 128; o; o >>= 1) { if (tid < o) red[tid] = fmaxf(red[tid], red[tid+o]); __syncthreads(); }
    mx = red[0];
    __syncthreads();
    float e0 = __expf(x0 - mx), e1 = __expf(x1 - mx);
    red[tid] = e0 + e1; __syncthreads();
    for (int o = 128; o; o >>= 1) { if (tid < o) red[tid] += red[tid+o]; __syncthreads(); }
    float inv = 1.f / red[0];
    p[tid]       = e0 * inv;
    p[tid + 256] = e1 * inv;
}

// ---------------- generic tf32 MMA GEMM (proven R6/R9 version, untouched) ----------------
#define GP 72
__global__ __launch_bounds__(128) void k_gemm_mma(
    const float* __restrict__ A, long sAb, int lda,
    const float* __restrict__ Bp, long sBb, int sbk, int sbn,
    float* __restrict__ C, long sCb, int ldc, int K,
    const float* __restrict__ bias, int dorelu,
    const float* __restrict__ alphap)
{
    __shared__ unsigned As[2][16][GP];   // [k][m], tf32 bits
    __shared__ unsigned Bs[2][16][GP];   // [k][n], tf32 bits
    int bz = blockIdx.z;
    A  += sAb * bz;  Bp += sBb * bz;  C += sCb * bz;
    int m0 = blockIdx.y * 64, n0 = blockIdx.x * 64;
    int tid  = threadIdx.x;
    int lane = tid & 31, wid = tid >> 5;
    int g = lane >> 2, c = lane & 3;
    int wm = (wid >> 1) * 32, wn = (wid & 1) * 32;

    int am  = tid >> 1, ak  = (tid & 1) * 8;
    int bk  = tid >> 3, bn  = (tid & 7) * 8;
    int bn2 = tid >> 1, bk2 = (tid & 1) * 8;
    bool brow = (sbn == 1);
    int ktiles = K >> 4;

    {   // stage 0
        float4 v0 = *(const float4*)&A[(long)(m0 + am) * lda + ak];
        float4 v1 = *(const float4*)&A[(long)(m0 + am) * lda + ak + 4];
        As[0][ak+0][am] = f2tf(v0.x); As[0][ak+1][am] = f2tf(v0.y);
        As[0][ak+2][am] = f2tf(v0.z); As[0][ak+3][am] = f2tf(v0.w);
        As[0][ak+4][am] = f2tf(v1.x); As[0][ak+5][am] = f2tf(v1.y);
        As[0][ak+6][am] = f2tf(v1.z); As[0][ak+7][am] = f2tf(v1.w);
        if (brow) {
            float4 w0 = *(const float4*)&Bp[(long)bk * sbk + n0 + bn];
            float4 w1 = *(const float4*)&Bp[(long)bk * sbk + n0 + bn + 4];
            Bs[0][bk][bn+0] = f2tf(w0.x); Bs[0][bk][bn+1] = f2tf(w0.y);
            Bs[0][bk][bn+2] = f2tf(w0.z); Bs[0][bk][bn+3] = f2tf(w0.w);
            Bs[0][bk][bn+4] = f2tf(w1.x); Bs[0][bk][bn+5] = f2tf(w1.y);
            Bs[0][bk][bn+6] = f2tf(w1.z); Bs[0][bk][bn+7] = f2tf(w1.w);
        } else {
            float4 w0 = *(const float4*)&Bp[(long)(n0 + bn2) * sbn + bk2];
            float4 w1 = *(const float4*)&Bp[(long)(n0 + bn2) * sbn + bk2 + 4];
            Bs[0][bk2+0][bn2] = f2tf(w0.x); Bs[0][bk2+1][bn2] = f2tf(w0.y);
            Bs[0][bk2+2][bn2] = f2tf(w0.z); Bs[0][bk2+3][bn2] = f2tf(w0.w);
            Bs[0][bk2+4][bn2] = f2tf(w1.x); Bs[0][bk2+5][bn2] = f2tf(w1.y);
            Bs[0][bk2+6][bn2] = f2tf(w1.z); Bs[0][bk2+7][bn2] = f2tf(w1.w);
        }
    }
    __syncthreads();

    float acc[2][4][4];
    #pragma unroll
    for (int mt = 0; mt < 2; mt++)
        #pragma unroll
        for (int nt = 0; nt < 4; nt++)
            #pragma unroll
            for (int q = 0; q < 4; q++) acc[mt][nt][q] = 0.f;

    int buf = 0;
    for (int t = 0; t < ktiles; t++) {
        float4 v0, v1, w0, w1;
        bool has = (t + 1 < ktiles);
        if (has) {
            int k0 = (t + 1) << 4;
            v0 = *(const float4*)&A[(long)(m0 + am) * lda + k0 + ak];
            v1 = *(const float4*)&A[(long)(m0 + am) * lda + k0 + ak + 4];
            if (brow) {
                w0 = *(const float4*)&Bp[(long)(k0 + bk) * sbk + n0 + bn];
                w1 = *(const float4*)&Bp[(long)(k0 + bk) * sbk + n0 + bn + 4];
            } else {
                w0 = *(const float4*)&Bp[(long)(n0 + bn2) * sbn + k0 + bk2];
                w1 = *(const float4*)&Bp[(long)(n0 + bn2) * sbn + k0 + bk2 + 4];
            }
        }
        #pragma unroll
        for (int kk = 0; kk < 16; kk += 8) {
            unsigned a[2][4], bf[4][2];
            #pragma unroll
            for (int mt = 0; mt < 2; mt++) {
                int mm = wm + mt * 16;
                a[mt][0] = As[buf][kk + c    ][mm + g];
                a[mt][1] = As[buf][kk + c    ][mm + g + 8];
                a[mt][2] = As[buf][kk + c + 4][mm + g];
                a[mt][3] = As[buf][kk + c + 4][mm + g + 8];
            }
            #pragma unroll
            for (int nt = 0; nt < 4; nt++) {
                bf[nt][0] = Bs[buf][kk + c    ][wn + nt * 8 + g];
                bf[nt][1] = Bs[buf][kk + c + 4][wn + nt * 8 + g];
            }
            #pragma unroll
            for (int mt = 0; mt < 2; mt++)
                #pragma unroll
                for (int nt = 0; nt < 4; nt++)
                    mma_tf32(acc[mt][nt][0], acc[mt][nt][1], acc[mt][nt][2], acc[mt][nt][3],
                             a[mt][0], a[mt][1], a[mt][2], a[mt][3], bf[nt][0], bf[nt][1]);
        }
        if (has) {
            int nb = buf ^ 1;
            As[nb][ak+0][am] = f2tf(v0.x); As[nb][ak+1][am] = f2tf(v0.y);
            As[nb][ak+2][am] = f2tf(v0.z); As[nb][ak+3][am] = f2tf(v0.w);
            As[nb][ak+4][am] = f2tf(v1.x); As[nb][ak+5][am] = f2tf(v1.y);
            As[nb][ak+6][am] = f2tf(v1.z); As[nb][ak+7][am] = f2tf(v1.w);
            if (brow) {
                Bs[nb][bk][bn+0] = f2tf(w0.x); Bs[nb][bk][bn+1] = f2tf(w0.y);
                Bs[nb][bk][bn+2] = f2tf(w0.z); Bs[nb][bk][bn+3] = f2tf(w0.w);
                Bs[nb][bk][bn+4] = f2tf(w1.x); Bs[nb][bk][bn+5] = f2tf(w1.y);
                Bs[nb][bk][bn+6] = f2tf(w1.z); Bs[nb][bk][bn+7] = f2tf(w1.w);
            } else {
                Bs[nb][bk2+0][bn2] = f2tf(w0.x); Bs[nb][bk2+1][bn2] = f2tf(w0.y);
                Bs[nb][bk2+2][bn2] = f2tf(w0.z); Bs[nb][bk2+3][bn2] = f2tf(w0.w);
                Bs[nb][bk2+4][bn2] = f2tf(w1.x); Bs[nb][bk2+5][bn2] = f2tf(w1.y);
                Bs[nb][bk2+6][bn2] = f2tf(w1.z); Bs[nb][bk2+7][bn2] = f2tf(w1.w);
            }
            __syncthreads();
            buf = nb;
        }
    }

    float al = alphap ? *alphap : 1.f;
    #pragma unroll
    for (int mt = 0; mt < 2; mt++) {
        int r0 = m0 + wm + mt * 16 + g;
        #pragma unroll
        for (int nt = 0; nt < 4; nt++) {
            int col = n0 + wn + nt * 8 + c * 2;
            float b0 = bias ? bias[col]     : 0.f;
            float b1 = bias ? bias[col + 1] : 0.f;
            float x0 = acc[mt][nt][0] + b0, x1 = acc[mt][nt][1] + b1;
            float x2 = acc[mt][nt][2] + b0, x3 = acc[mt][nt][3] + b1;
            if (dorelu) { x0 = fmaxf(x0,0.f); x1 = fmaxf(x1,0.f); x2 = fmaxf(x2,0.f); x3 = fmaxf(x3,0.f); }
            *(float2*)&C[(long)r0 * ldc + col]       = make_float2(x0 * al, x1 * al);
            *(float2*)&C[(long)(r0 + 8) * ldc + col] = make_float2(x2 * al, x3 * al);
        }
    }
}

// ---------------- GEMM for v-MLP layer 1 with fused msgin A-synthesis -------------
// A[r][k] = k<768: ctx[r][k];  k<1536: Hj[r][k-768];  else ctx[r][k-1536]*Hj[r][k-1536]
// Same 64x64x16 structure as k_gemm_mma, B = vw1 (NxK), bias+relu epilogue.
// Concat boundaries (768,1536) are 16-aligned -> region uniform per (thread, ktile).
__global__ __launch_bounds__(128) void k_gemm_mlp1(
    const float* __restrict__ ctx, const float* __restrict__ Hjp,
    const float* __restrict__ Bp,  // vw1 [OHv][K3H]
    float* __restrict__ C,         // g_hid1 [Rv][OHv]
    const float* __restrict__ bias)
{
    __shared__ unsigned As[2][16][GP];
    __shared__ unsigned Bs[2][16][GP];
    int m0 = blockIdx.y * 64, n0 = blockIdx.x * 64;
    int tid  = threadIdx.x;
    int lane = tid & 31, wid = tid >> 5;
    int g = lane >> 2, c = lane & 3;
    int wm = (wid >> 1) * 32, wn = (wid & 1) * 32;

    int am  = tid >> 1, ak  = (tid & 1) * 8;
    int bn2 = tid >> 1, bk2 = (tid & 1) * 8;
    const int ktiles = K3H >> 4;   // 144
    const float* crow = ctx + (long)(m0 + am) * Hv;
    const float* hrow = Hjp + (long)(m0 + am) * Hv;

    // A fragment synthesizer for k in [kpos, kpos+8)
    auto loadA = [&](int kpos, float4& v0, float4& v1) {
        int reg = kpos / Hv;
        int kk  = kpos - reg * Hv;
        if (reg == 0) {
            v0 = *(const float4*)&crow[kk];     v1 = *(const float4*)&crow[kk + 4];
        } else if (reg == 1) {
            v0 = *(const float4*)&hrow[kk];     v1 = *(const float4*)&hrow[kk + 4];
        } else {
            float4 c0 = *(const float4*)&crow[kk], c1 = *(const float4*)&crow[kk + 4];
            float4 h0 = *(const float4*)&hrow[kk], h1 = *(const float4*)&hrow[kk + 4];
            v0 = make_float4(c0.x*h0.x, c0.y*h0.y, c0.z*h0.z, c0.w*h0.w);
            v1 = make_float4(c1.x*h1.x, c1.y*h1.y, c1.z*h1.z, c1.w*h1.w);
        }
    };

    {   // stage 0
        float4 v0, v1;
        loadA(ak, v0, v1);
        As[0][ak+0][am] = f2tf(v0.x); As[0][ak+1][am] = f2tf(v0.y);
        As[0][ak+2][am] = f2tf(v0.z); As[0][ak+3][am] = f2tf(v0.w);
        As[0][ak+4][am] = f2tf(v1.x); As[0][ak+5][am] = f2tf(v1.y);
        As[0][ak+6][am] = f2tf(v1.z); As[0][ak+7][am] = f2tf(v1.w);
        float4 w0 = *(const float4*)&Bp[(long)(n0 + bn2) * K3H + bk2];
        float4 w1 = *(const float4*)&Bp[(long)(n0 + bn2) * K3H + bk2 + 4];
        Bs[0][bk2+0][bn2] = f2tf(w0.x); Bs[0][bk2+1][bn2] = f2tf(w0.y);
        Bs[0][bk2+2][bn2] = f2tf(w0.z); Bs[0][bk2+3][bn2] = f2tf(w0.w);
        Bs[0][bk2+4][bn2] = f2tf(w1.x); Bs[0][bk2+5][bn2] = f2tf(w1.y);
        Bs[0][bk2+6][bn2] = f2tf(w1.z); Bs[0][bk2+7][bn2] = f2tf(w1.w);
    }
    __syncthreads();

    float acc[2][4][4];
    #pragma unroll
    for (int mt = 0; mt < 2; mt++)
        #pragma unroll
        for (int nt = 0; nt < 4; nt++)
            #pragma unroll
            for (int q = 0; q < 4; q++) acc[mt][nt][q] = 0.f;

    int buf = 0;
    for (int t = 0; t < ktiles; t++) {
        float4 v0, v1, w0, w1;
        bool has = (t + 1 < ktiles);
        if (has) {
            int k0 = (t + 1) << 4;
            loadA(k0 + ak, v0, v1);
            w0 = *(const float4*)&Bp[(long)(n0 + bn2) * K3H + k0 + bk2];
            w1 = *(const float4*)&Bp[(long)(n0 + bn2) * K3H + k0 + bk2 + 4];
        }
        #pragma unroll
        for (int kk = 0; kk < 16; kk += 8) {
            unsigned a[2][4], bf[4][2];
            #pragma unroll
            for (int mt = 0; mt < 2; mt++) {
                int mm = wm + mt * 16;
                a[mt][0] = As[buf][kk + c    ][mm + g];
                a[mt][1] = As[buf][kk + c    ][mm + g + 8];
                a[mt][2] = As[buf][kk + c + 4][mm + g];
                a[mt][3] = As[buf][kk + c + 4][mm + g + 8];
            }
            #pragma unroll
            for (int nt = 0; nt < 4; nt++) {
                bf[nt][0] = Bs[buf][kk + c    ][wn + nt * 8 + g];
                bf[nt][1] = Bs[buf][kk + c + 4][wn + nt * 8 + g];
            }
            #pragma unroll
            for (int mt = 0; mt < 2; mt++)
                #pragma unroll
                for (int nt = 0; nt < 4; nt++)
                    mma_tf32(acc[mt][nt][0], acc[mt][nt][1], acc[mt][nt][2], acc[mt][nt][3],
                             a[mt][0], a[mt][1], a[mt][2], a[mt][3], bf[nt][0], bf[nt][1]);
        }
        if (has) {
            int nb = buf ^ 1;
            As[nb][ak+0][am] = f2tf(v0.x); As[nb][ak+1][am] = f2tf(v0.y);
            As[nb][ak+2][am] = f2tf(v0.z); As[nb][ak+3][am] = f2tf(v0.w);
            As[nb][ak+4][am] = f2tf(v1.x); As[nb][ak+5][am] = f2tf(v1.y);
            As[nb][ak+6][am] = f2tf(v1.z); As[nb][ak+7][am] = f2tf(v1.w);
            Bs[nb][bk2+0][bn2] = f2tf(w0.x); Bs[nb][bk2+1][bn2] = f2tf(w0.y);
            Bs[nb][bk2+2][bn2] = f2tf(w0.z); Bs[nb][bk2+3][bn2] = f2tf(w0.w);
            Bs[nb][bk2+4][bn2] = f2tf(w1.x); Bs[nb][bk2+5][bn2] = f2tf(w1.y);
            Bs[nb][bk2+6][bn2] = f2tf(w1.z); Bs[nb][bk2+7][bn2] = f2tf(w1.w);
            __syncthreads();
            buf = nb;
        }
    }

    #pragma unroll
    for (int mt = 0; mt < 2; mt++) {
        int r0 = m0 + wm + mt * 16 + g;
        #pragma unroll
        for (int nt = 0; nt < 4; nt++) {
            int col = n0 + wn + nt * 8 + c * 2;
            float b0 = bias[col], b1 = bias[col + 1];
            float x0 = fmaxf(acc[mt][nt][0] + b0, 0.f);
            float x1 = fmaxf(acc[mt][nt][1] + b1, 0.f);
            float x2 = fmaxf(acc[mt][nt][2] + b0, 0.f);
            float x3 = fmaxf(acc[mt][nt][3] + b1, 0.f);
            *(float2*)&C[(long)r0 * OHv + col]       = make_float2(x0, x1);
            *(float2*)&C[(long)(r0 + 8) * OHv + col] = make_float2(x2, x3);
        }
    }
}

// ---------------- launch ----------------
extern "C" void kernel_launch(void* const* d_in, const int* in_sizes, int n_in,
                              void* d_out, int out_size)
{
    const float* Hj    = (const float*)d_in[0];
    const float* Hi    = (const float*)d_in[1];
    const float* mask  = (const float*)d_in[2];
    const float* pjw   = (const float*)d_in[3];
    const float* piw   = (const float*)d_in[4];
    const float* sw1   = (const float*)d_in[5];
    const float* sb1   = (const float*)d_in[6];
    const float* sw2   = (const float*)d_in[7];
    const float* sb2   = (const float*)d_in[8];
    const float* vw1   = (const float*)d_in[9];
    const float* vb1   = (const float*)d_in[10];
    const float* vw2   = (const float*)d_in[11];
    const float* vb2   = (const float*)d_in[12];
    const float* alpha = (const float*)d_in[13];
    float* out = (float*)d_out;
    (void)in_sizes; (void)n_in; (void)out_size;

    void *pP, *pCtx, *pH1;
    cudaGetSymbolAddress(&pP,   g_P);
    cudaGetSymbolAddress(&pCtx, g_ctx);
    cudaGetSymbolAddress(&pH1,  g_hid1);

    // 0) weight prep (permute + tf32 + fragment layout)
    k_prep<<<36, 256>>>(sw1, sw2, sb1);
    // 1) projections
    k_proj<<<dim3(Rv, 2), 256>>>(Hj, Hi, pjw, piw);
    // 2) pairwise MLP logits (TT=64)
    k_logits3<<<dim3(Sv/TT, Sv/ST, Bv), 256>>>(sb2);
    // 3) masked softmax
    k_softmax<<<Rv, 256>>>(mask);
    // 4) ctx = probs @ H_i   (batched over b)
    k_gemm_mma<<<dim3(Hv/64, Sv/64, Bv), 128>>>(
        (const float*)pP, (long)Sv*Sv, Sv,
        Hi, (long)Sv*Hv, Hv, 1,
        (float*)pCtx, (long)Sv*Hv, Hv, Sv,
        nullptr, 0, nullptr);
    // 5) hid1 = relu([ctx,Hj,ctx*Hj] @ v_w1.T + b1)   (msgin fused into A-staging)
    k_gemm_mlp1<<<dim3(OHv/64, Rv/64, 1), 128>>>(
        (const float*)pCtx, Hj, vw1, (float*)pH1, vb1);
    // 6) out = alpha * (hid1 @ v_w2.T + b2)
    k_gemm_mma<<<dim3(Hv/64, Rv/64, 1), 128>>>(
        (const float*)pH1, 0L, OHv,
        vw2, 0L, 1, OHv,
        out, 0L, Hv, OHv,
        vb2, 0, alpha);
}

// round 15
// speedup vs baseline: 1.4901x; 1.1633x over previous
#include <cuda_runtime.h>

#define Bv 4
#define Sv 512
#define Hv 768
#define Dv 24
#define Mv 96
#define OHv 768
#define Rv (Bv*Sv)        /* 2048 */
#define K3H (3*Hv)        /* 2304 */

// ---------------- scratch (device globals; no runtime allocation) ----------------
__device__ float g_Zj[Rv*Dv];
__device__ float g_Zi[Rv*Dv];
__device__ float g_P[(long)Bv*Sv*Sv];  // logits -> probs (4 MB)
__device__ float g_ctx[(long)Rv*Hv];
__device__ float g_msgin[(long)Rv*K3H];
__device__ float g_hid1[(long)Rv*OHv];
__device__ __align__(16) unsigned g_Wf[12*12*32*2];  // permuted tf32 weights, fragment layout
__device__ float2 g_pw[Mv];                           // (w2[m], b1[m])

// ---------------- tf32 helpers ----------------
__device__ __forceinline__ unsigned f2tf(float x) {
    unsigned r;
    asm("cvt.rna.tf32.f32 %0, %1;" : "=r"(r) : "f"(x));
    return r;
}
__device__ __forceinline__ void mma_tf32(float& c0, float& c1, float& c2, float& c3,
                                         unsigned a0, unsigned a1, unsigned a2, unsigned a3,
                                         unsigned b0, unsigned b1) {
    asm volatile("mma.sync.aligned.m16n8k8.row.col.f32.tf32.tf32.f32 "
                 "{%0,%1,%2,%3},{%4,%5,%6,%7},{%8,%9},{%0,%1,%2,%3};"
                 : "+f"(c0), "+f"(c1), "+f"(c2), "+f"(c3)
                 : "r"(a0), "r"(a1), "r"(a2), "r"(a3), "r"(b0), "r"(b1));
}
__device__ __forceinline__ void cp16(unsigned smem_addr, const void* gptr) {
    asm volatile("cp.async.cg.shared.global [%0], [%1], 16;" :: "r"(smem_addr), "l"(gptr));
}
__device__ __forceinline__ void cp_commit() {
    asm volatile("cp.async.commit_group;");
}
__device__ __forceinline__ void cp_wait2() {
    asm volatile("cp.async.wait_group 2;");
}

// ---------------- K0: one-time weight prep (permute + tf32 + fragment layout) ----------------
__global__ __launch_bounds__(256) void k_prep(const float* __restrict__ sw1,
                                              const float* __restrict__ sw2,
                                              const float* __restrict__ sb1)
{
    int idx = blockIdx.x * 256 + threadIdx.x;
    if (idx < Mv * 96) {
        int m = idx / 96, k = idx - m * 96;
        int src;
        if (k < 24)      src = 48 + k;
        else if (k < 48) src = 72 + (k - 24);
        else if (k < 72) src = k - 48;
        else             src = 24 + (k - 72);
        int kt = k >> 3, kr = k & 7, c = kr & 3, reg = kr >> 2;
        int nt = m >> 3, g = m & 7;
        g_Wf[((kt*12 + nt)*32 + g*4 + c)*2 + reg] = f2tf(sw1[m * 96 + src]);
    }
    if (blockIdx.x == 0 && threadIdx.x < Mv)
        g_pw[threadIdx.x] = make_float2(sw2[threadIdx.x], sb1[threadIdx.x]);
}

// ---------------- K1: projections Zj/Zi ----------------
__global__ __launch_bounds__(256) void k_proj(const float* __restrict__ Hj,
                                              const float* __restrict__ Hi,
                                              const float* __restrict__ pj,
                                              const float* __restrict__ pi)
{
    int row   = blockIdx.x;
    int which = blockIdx.y;
    const float* Hm = which ? Hi : Hj;
    const float* Pw = which ? pi : pj;
    __shared__ float sh[Hv];
    int tid = threadIdx.x;
    const float* hrow = Hm + (long)row * Hv;
    for (int i = tid; i < Hv; i += 256) sh[i] = hrow[i];
    __syncthreads();
    int warp = tid >> 5, lane = tid & 31;
    for (int d = warp; d < Dv; d += 8) {
        const float* pr = Pw + d * Hv;
        float acc = 0.f;
        for (int i = lane; i < Hv; i += 32) acc += sh[i] * pr[i];
        #pragma unroll
        for (int o = 16; o; o >>= 1) acc += __shfl_down_sync(0xFFFFFFFFu, acc, o);
        if (lane == 0) (which ? g_Zi : g_Zj)[row * Dv + d] = acc;
    }
}

// ---------------- K2: pairwise MLP -> logits via tf32 MMA (R14: TT=64) ----------------
#define ST 8
#define TT 64
__global__ __launch_bounds__(256) void k_logits3(const float* __restrict__ sb2)
{
    __shared__ __align__(16) unsigned Ws[12*12*32*2];   // 36 KB fragment-layout weights
    __shared__ float2 pw[Mv];
    __shared__ float Zjs[ST][25];
    __shared__ float Zis[TT][25];
    int b  = blockIdx.z;
    int s0 = blockIdx.y * ST;
    int t0 = blockIdx.x * TT;
    int tid = threadIdx.x;

    {   // stage weights: 9216 u32 = 2304 uint4, 9 per thread
        const uint4* src = (const uint4*)g_Wf;
        uint4* dst = (uint4*)Ws;
        #pragma unroll
        for (int i = 0; i < 9; i++) dst[tid + i * 256] = src[tid + i * 256];
    }
    if (tid < Mv) pw[tid] = g_pw[tid];
    for (int i = tid; i < ST * Dv; i += 256)
        Zjs[i / Dv][i % Dv] = g_Zj[(b * Sv + s0 + i / Dv) * Dv + (i % Dv)];
    for (int i = tid; i < TT * Dv; i += 256)
        Zis[i / Dv][i % Dv] = g_Zi[(b * Sv + t0 + i / Dv) * Dv + (i % Dv)];
    __syncthreads();

    int wid  = tid >> 5, lane = tid & 31;
    int g = lane >> 2, c = lane & 3;
    float b2 = sb2[0];

    #pragma unroll
    for (int tt = 0; tt < TT/16; tt++) {
        const int toff = tt * 16;
        float acc[12][4];
        #pragma unroll
        for (int nt = 0; nt < 12; nt++)
            #pragma unroll
            for (int q = 0; q < 4; q++) acc[nt][q] = 0.f;

        #pragma unroll
        for (int ks = 0; ks < 12; ks++) {
            const int k0 = ks * 8;
            const int op = k0 / 24;
            const int d0 = k0 % 24;
            int d  = d0 + c;
            int d4 = d0 + c + 4;
            unsigned a0, a1, a2, a3;
            if (op == 0) {               // Zj * Zi
                float zj = Zjs[wid][d], zj4 = Zjs[wid][d4];
                a0 = f2tf(zj  * Zis[toff + g][d]);   a1 = f2tf(zj  * Zis[toff + g + 8][d]);
                a2 = f2tf(zj4 * Zis[toff + g][d4]);  a3 = f2tf(zj4 * Zis[toff + g + 8][d4]);
            } else if (op == 1) {        // |Zj - Zi|
                float zj = Zjs[wid][d], zj4 = Zjs[wid][d4];
                a0 = f2tf(fabsf(zj  - Zis[toff + g][d]));   a1 = f2tf(fabsf(zj  - Zis[toff + g + 8][d]));
                a2 = f2tf(fabsf(zj4 - Zis[toff + g][d4]));  a3 = f2tf(fabsf(zj4 - Zis[toff + g + 8][d4]));
            } else if (op == 2) {        // Zj (t-invariant)
                unsigned u = f2tf(Zjs[wid][d]), u4 = f2tf(Zjs[wid][d4]);
                a0 = u; a1 = u; a2 = u4; a3 = u4;
            } else {                     // Zi
                a0 = f2tf(Zis[toff + g][d]);   a1 = f2tf(Zis[toff + g + 8][d]);
                a2 = f2tf(Zis[toff + g][d4]);  a3 = f2tf(Zis[toff + g + 8][d4]);
            }
            #pragma unroll
            for (int nt = 0; nt < 12; nt++) {
                uint2 bv = *(const uint2*)&Ws[((ks*12 + nt)*32 + lane)*2];
                mma_tf32(acc[nt][0], acc[nt][1], acc[nt][2], acc[nt][3],
                         a0, a1, a2, a3, bv.x, bv.y);
            }
        }

        float r0 = 0.f, r1 = 0.f;
        #pragma unroll
        for (int nt = 0; nt < 12; nt++) {
            int m = nt * 8 + c * 2;
            float2 p0 = pw[m], p1 = pw[m + 1];
            r0 += fmaxf(acc[nt][0] + p0.y, 0.f) * p0.x + fmaxf(acc[nt][1] + p1.y, 0.f) * p1.x;
            r1 += fmaxf(acc[nt][2] + p0.y, 0.f) * p0.x + fmaxf(acc[nt][3] + p1.y, 0.f) * p1.x;
        }
        r0 += __shfl_xor_sync(0xFFFFFFFFu, r0, 1);
        r0 += __shfl_xor_sync(0xFFFFFFFFu, r0, 2);
        r1 += __shfl_xor_sync(0xFFFFFFFFu, r1, 1);
        r1 += __shfl_xor_sync(0xFFFFFFFFu, r1, 2);
        if (c == 0) {
            long base = ((long)(b * Sv + s0 + wid)) * Sv + t0 + toff;
            g_P[base + g]     = r0 + b2;
            g_P[base + g + 8] = r1 + b2;
        }
    }
}

// ---------------- K3: masked softmax over t ----------------
__global__ __launch_bounds__(256) void k_softmax(const float* __restrict__ mask)
{
    int row = blockIdx.x;
    int b = row >> 9;
    float* p = g_P + (long)row * Sv;
    int tid = threadIdx.x;
    __shared__ float red[256];
    const float NEG = -3.402823466e38f;
    float x0 = p[tid]       + (1.f - mask[b*Sv + tid])       * NEG;
    float x1 = p[tid + 256] + (1.f - mask[b*Sv + tid + 256]) * NEG;
    float mx = fmaxf(x0, x1);
    red[tid] = mx; __syncthreads();
    for (int o = 128; o; o >>= 1) { if (tid < o) red[tid] = fmaxf(red[tid], red[tid+o]); __syncthreads(); }
    mx = red[0];
    __syncthreads();
    float e0 = __expf(x0 - mx), e1 = __expf(x1 - mx);
    red[tid] = e0 + e1; __syncthreads();
    for (int o = 128; o; o >>= 1) { if (tid < o) red[tid] += red[tid+o]; __syncthreads(); }
    float inv = 1.f / red[0];
    p[tid]       = e0 * inv;
    p[tid + 256] = e1 * inv;
}

// ---------------- tf32 MMA GEMM v5: cp.async 4-stage pipeline -----------------
// A row-major [M][lda]; B element [k][n] at Bp[k*sbk + n*sbn]
// (sbn==1: row-major KxN; sbk==1: NxK weights -> A@W.T)
// 64x64x16 tiles, 128 threads, warp 32x32, 4 smem stages, fp32 in smem,
// cvt.rna.tf32 at fragment load (same operand bits as before -> same numerics).
// Smem layouts (per stage, 1280 floats):
//   A:        [m(64)][k(16) pad 20]   -> fragment LDS conflict-free (20g+c distinct mod 32)
//   B row:    [k(16)][n(64) pad 72]   -> (8c+g) distinct mod 32
//   B weight: [n(64)][k(16) pad 20]
#define STAGES 4
#define STRIDE_AK 20
#define STRIDE_BN 72
__global__ __launch_bounds__(128) void k_gemm_cp(
    const float* __restrict__ A, long sAb, int lda,
    const float* __restrict__ Bp, long sBb, int sbk, int sbn,
    float* __restrict__ C, long sCb, int ldc, int K,
    const float* __restrict__ bias, int dorelu,
    const float* __restrict__ alphap)
{
    __shared__ __align__(16) float As[STAGES][1280];
    __shared__ __align__(16) float Bs[STAGES][1280];
    int bz = blockIdx.z;
    A  += sAb * bz;  Bp += sBb * bz;  C += sCb * bz;
    int m0 = blockIdx.y * 64, n0 = blockIdx.x * 64;
    int tid  = threadIdx.x;
    int lane = tid & 31, wid = tid >> 5;
    int g = lane >> 2, c = lane & 3;
    int wm = (wid >> 1) * 32, wn = (wid & 1) * 32;
    bool brow = (sbn == 1);
    int ktiles = K >> 4;

    // per-thread cp.async chunks (2 for A, 2 for B)
    int a_row0 = tid >> 2,            a_kq = (tid & 3) * 4;        // chunks tid, tid+128
    int brow_k0 = tid >> 4,           brow_nq = (tid & 15) * 4;
    int bwt_n0  = tid >> 2,           bwt_kq  = (tid & 3) * 4;

    unsigned sA = (unsigned)__cvta_generic_to_shared(&As[0][0]);
    unsigned sB = (unsigned)__cvta_generic_to_shared(&Bs[0][0]);

    auto issue = [&](int t, int st) {
        int k0 = t << 4;
        unsigned aBase = sA + st * 1280 * 4;
        unsigned bBase = sB + st * 1280 * 4;
        // A: rows a_row0, a_row0+32
        cp16(aBase + (a_row0      * STRIDE_AK + a_kq) * 4, &A[(long)(m0 + a_row0)      * lda + k0 + a_kq]);
        cp16(aBase + ((a_row0+32) * STRIDE_AK + a_kq) * 4, &A[(long)(m0 + a_row0 + 32) * lda + k0 + a_kq]);
        if (brow) {
            cp16(bBase + (brow_k0     * STRIDE_BN + brow_nq) * 4, &Bp[(long)(k0 + brow_k0)     * sbk + n0 + brow_nq]);
            cp16(bBase + ((brow_k0+8) * STRIDE_BN + brow_nq) * 4, &Bp[(long)(k0 + brow_k0 + 8) * sbk + n0 + brow_nq]);
        } else {
            cp16(bBase + (bwt_n0      * STRIDE_AK + bwt_kq) * 4, &Bp[(long)(n0 + bwt_n0)      * sbn + k0 + bwt_kq]);
            cp16(bBase + ((bwt_n0+32) * STRIDE_AK + bwt_kq) * 4, &Bp[(long)(n0 + bwt_n0 + 32) * sbn + k0 + bwt_kq]);
        }
    };

    // prologue: stages 0..2
    #pragma unroll
    for (int s = 0; s < STAGES - 1; s++) {
        if (s < ktiles) issue(s, s);
        cp_commit();
    }

    float acc[2][4][4];
    #pragma unroll
    for (int mt = 0; mt < 2; mt++)
        #pragma unroll
        for (int nt = 0; nt < 4; nt++)
            #pragma unroll
            for (int q = 0; q < 4; q++) acc[mt][nt][q] = 0.f;

    for (int t = 0; t < ktiles; t++) {
        cp_wait2();
        __syncthreads();
        int tn = t + STAGES - 1;
        if (tn < ktiles) issue(tn, tn & (STAGES - 1));
        cp_commit();

        int st = t & (STAGES - 1);
        const float* Ast = As[st];
        const float* Bst = Bs[st];
        #pragma unroll
        for (int kk = 0; kk < 16; kk += 8) {
            unsigned a[2][4], bf[4][2];
            #pragma unroll
            for (int mt = 0; mt < 2; mt++) {
                int mm = wm + mt * 16;
                a[mt][0] = f2tf(Ast[(mm + g)     * STRIDE_AK + kk + c]);
                a[mt][1] = f2tf(Ast[(mm + g + 8) * STRIDE_AK + kk + c]);
                a[mt][2] = f2tf(Ast[(mm + g)     * STRIDE_AK + kk + c + 4]);
                a[mt][3] = f2tf(Ast[(mm + g + 8) * STRIDE_AK + kk + c + 4]);
            }
            if (brow) {
                #pragma unroll
                for (int nt = 0; nt < 4; nt++) {
                    int nn = wn + nt * 8 + g;
                    bf[nt][0] = f2tf(Bst[(kk + c)     * STRIDE_BN + nn]);
                    bf[nt][1] = f2tf(Bst[(kk + c + 4) * STRIDE_BN + nn]);
                }
            } else {
                #pragma unroll
                for (int nt = 0; nt < 4; nt++) {
                    int nn = wn + nt * 8 + g;
                    bf[nt][0] = f2tf(Bst[nn * STRIDE_AK + kk + c]);
                    bf[nt][1] = f2tf(Bst[nn * STRIDE_AK + kk + c + 4]);
                }
            }
            #pragma unroll
            for (int mt = 0; mt < 2; mt++)
                #pragma unroll
                for (int nt = 0; nt < 4; nt++)
                    mma_tf32(acc[mt][nt][0], acc[mt][nt][1], acc[mt][nt][2], acc[mt][nt][3],
                             a[mt][0], a[mt][1], a[mt][2], a[mt][3], bf[nt][0], bf[nt][1]);
        }
    }

    float al = alphap ? *alphap : 1.f;
    #pragma unroll
    for (int mt = 0; mt < 2; mt++) {
        int r0 = m0 + wm + mt * 16 + g;
        #pragma unroll
        for (int nt = 0; nt < 4; nt++) {
            int col = n0 + wn + nt * 8 + c * 2;
            float b0 = bias ? bias[col]     : 0.f;
            float b1 = bias ? bias[col + 1] : 0.f;
            float x0 = acc[mt][nt][0] + b0, x1 = acc[mt][nt][1] + b1;
            float x2 = acc[mt][nt][2] + b0, x3 = acc[mt][nt][3] + b1;
            if (dorelu) { x0 = fmaxf(x0,0.f); x1 = fmaxf(x1,0.f); x2 = fmaxf(x2,0.f); x3 = fmaxf(x3,0.f); }
            *(float2*)&C[(long)r0 * ldc + col]       = make_float2(x0 * al, x1 * al);
            *(float2*)&C[(long)(r0 + 8) * ldc + col] = make_float2(x2 * al, x3 * al);
        }
    }
}

// ---------------- msg_in = [ctx, H_j, ctx*H_j] ----------------
__global__ __launch_bounds__(256) void k_msgin(const float* __restrict__ Hj)
{
    int i = blockIdx.x * 256 + threadIdx.x;
    if (i < Rv * Hv) {
        int r = i / Hv, h = i - r * Hv;
        float cx = g_ctx[i];
        float x = Hj[i];
        long base = (long)r * K3H + h;
        g_msgin[base]        = cx;
        g_msgin[base + Hv]   = x;
        g_msgin[base + 2*Hv] = cx * x;
    }
}

// ---------------- launch ----------------
extern "C" void kernel_launch(void* const* d_in, const int* in_sizes, int n_in,
                              void* d_out, int out_size)
{
    const float* Hj    = (const float*)d_in[0];
    const float* Hi    = (const float*)d_in[1];
    const float* mask  = (const float*)d_in[2];
    const float* pjw   = (const float*)d_in[3];
    const float* piw   = (const float*)d_in[4];
    const float* sw1   = (const float*)d_in[5];
    const float* sb1   = (const float*)d_in[6];
    const float* sw2   = (const float*)d_in[7];
    const float* sb2   = (const float*)d_in[8];
    const float* vw1   = (const float*)d_in[9];
    const float* vb1   = (const float*)d_in[10];
    const float* vw2   = (const float*)d_in[11];
    const float* vb2   = (const float*)d_in[12];
    const float* alpha = (const float*)d_in[13];
    float* out = (float*)d_out;
    (void)in_sizes; (void)n_in; (void)out_size;

    void *pP, *pCtx, *pMsg, *pH1;
    cudaGetSymbolAddress(&pP,   g_P);
    cudaGetSymbolAddress(&pCtx, g_ctx);
    cudaGetSymbolAddress(&pMsg, g_msgin);
    cudaGetSymbolAddress(&pH1,  g_hid1);

    // 0) weight prep (permute + tf32 + fragment layout)
    k_prep<<<36, 256>>>(sw1, sw2, sb1);
    // 1) projections
    k_proj<<<dim3(Rv, 2), 256>>>(Hj, Hi, pjw, piw);
    // 2) pairwise MLP logits (TT=64)
    k_logits3<<<dim3(Sv/TT, Sv/ST, Bv), 256>>>(sb2);
    // 3) masked softmax
    k_softmax<<<Rv, 256>>>(mask);
    // 4) ctx = probs @ H_i   (batched over b)
    k_gemm_cp<<<dim3(Hv/64, Sv/64, Bv), 128>>>(
        (const float*)pP, (long)Sv*Sv, Sv,
        Hi, (long)Sv*Hv, Hv, 1,
        (float*)pCtx, (long)Sv*Hv, Hv, Sv,
        nullptr, 0, nullptr);
    // 5) msg_in concat
    k_msgin<<<(Rv*Hv + 255)/256, 256>>>(Hj);
    // 6) hid1 = relu(msg_in @ v_w1.T + b1)
    k_gemm_cp<<<dim3(OHv/64, Rv/64, 1), 128>>>(
        (const float*)pMsg, 0L, K3H,
        vw1, 0L, 1, K3H,
        (float*)pH1, 0L, OHv, K3H,
        vb1, 1, nullptr);
    // 7) out = alpha * (hid1 @ v_w2.T + b2)
    k_gemm_cp<<<dim3(Hv/64, Rv/64, 1), 128>>>(
        (const float*)pH1, 0L, OHv,
        vw2, 0L, 1, OHv,
        out, 0L, Hv, OHv,
        vb2, 0, alpha);
}